// round 1
// baseline (speedup 1.0000x reference)
#include <cuda_runtime.h>
#include <cuda_bf16.h>

// x: (8, 320, 128, 128) fp32, out same.
// out(c,p) = (silu(x[S(p)]) + x[p]) * (sigmoid(silu(x[S2(p)])) - 0.5)
// S per channel: c%5==0: j+1 ; 1: j-1 ; 2: i+1 ; 3: i-1 ; 4: identity (circular)

#define HH 128
#define WW 128
#define PLANE (HH*WW)
#define NCH 320
#define NROWS (8*NCH*HH)   // 327680 warps of work (one row each)

__device__ __forceinline__ float sigm(float a) {
    float e = __expf(-a);
    return __fdividef(1.0f, 1.0f + e);
}

__device__ __forceinline__ float outval(float x0, float x1, float x2) {
    float f1 = x1 * sigm(x1);            // silu at S(p)
    float f2 = x2 * sigm(x2);            // silu at S^2(p)
    float fatt = sigm(f2) - 0.5f;
    return (f1 + x0) * fatt;
}

__global__ __launch_bounds__(256, 8)
void ablock_kernel(const float* __restrict__ x, float* __restrict__ out) {
    const int lane = threadIdx.x & 31;
    const int wrp  = threadIdx.x >> 5;
    const int row_id = blockIdx.x * 8 + wrp;        // < 327680
    const int i  = row_id & 127;                    // row within plane
    const int bc = row_id >> 7;                     // plane index (b*320+c)
    const int c  = bc % NCH;
    const int s  = c % 5;                           // warp-uniform
    const float* plane = x   + (long long)bc * PLANE;
    float*      oplane = out + (long long)bc * PLANE;
    const int j0 = lane << 2;
    const float* row = plane + i * WW;

    float4 a = *(const float4*)(row + j0);
    float4 r;

    if (s == 4) {
        r.x = outval(a.x, a.x, a.x);
        r.y = outval(a.y, a.y, a.y);
        r.z = outval(a.z, a.z, a.z);
        r.w = outval(a.w, a.w, a.w);
    } else if (s == 0) {
        // S(j)=j+1, S2(j)=j+2 (mod 128)
        float4 b = *(const float4*)(row + ((j0 + 4) & 127));
        r.x = outval(a.x, a.y, a.z);
        r.y = outval(a.y, a.z, a.w);
        r.z = outval(a.z, a.w, b.x);
        r.w = outval(a.w, b.x, b.y);
    } else if (s == 1) {
        // S(j)=j-1, S2(j)=j-2 (mod 128)
        float4 b = *(const float4*)(row + ((j0 + 124) & 127));
        r.x = outval(a.x, b.w, b.z);
        r.y = outval(a.y, a.x, b.w);
        r.z = outval(a.z, a.y, a.x);
        r.w = outval(a.w, a.z, a.y);
    } else if (s == 2) {
        // S(i)=i+1, S2(i)=i+2 (mod 128)
        const float* r1 = plane + (((i + 1) & 127) * WW);
        const float* r2 = plane + (((i + 2) & 127) * WW);
        float4 b = *(const float4*)(r1 + j0);
        float4 d = *(const float4*)(r2 + j0);
        r.x = outval(a.x, b.x, d.x);
        r.y = outval(a.y, b.y, d.y);
        r.z = outval(a.z, b.z, d.z);
        r.w = outval(a.w, b.w, d.w);
    } else {
        // s == 3: S(i)=i-1, S2(i)=i-2 (mod 128)
        const float* r1 = plane + (((i + 127) & 127) * WW);
        const float* r2 = plane + (((i + 126) & 127) * WW);
        float4 b = *(const float4*)(r1 + j0);
        float4 d = *(const float4*)(r2 + j0);
        r.x = outval(a.x, b.x, d.x);
        r.y = outval(a.y, b.y, d.y);
        r.z = outval(a.z, b.z, d.z);
        r.w = outval(a.w, b.w, d.w);
    }

    *(float4*)(oplane + i * WW + j0) = r;
}

extern "C" void kernel_launch(void* const* d_in, const int* in_sizes, int n_in,
                              void* d_out, int out_size) {
    const float* x = (const float*)d_in[0];
    float* out = (float*)d_out;
    dim3 grid(NROWS / 8);   // 40960 blocks, 8 warps (rows) each
    dim3 block(256);
    ablock_kernel<<<grid, block>>>(x, out);
}

// round 2
// speedup vs baseline: 1.0746x; 1.0746x over previous
#include <cuda_runtime.h>
#include <cuda_bf16.h>

// x: (8, 320, 128, 128) fp32, out same.
// out(c,p) = (silu(x[S(p)]) + x[p]) * (sigmoid(silu(x[S2(p)])) - 0.5)
// S per channel: c%5==0: j+1 ; 1: j-1 ; 2: i+1 ; 3: i-1 ; 4: identity (circular)

#define HH 128
#define WW 128
#define PLANE (HH*WW)
#define NCH 320

// warp handles 4 consecutive rows in one plane; 8 warps/block
// groups = 8*320*(128/4) = 81920 ; blocks = 81920/8 = 10240
#define NGROUPS (8*NCH*(HH/4))

__device__ __forceinline__ float tanh_fast(float a) {
    float r;
    asm("tanh.approx.f32 %0, %1;" : "=f"(r) : "f"(a));
    return r;
}

// silu via tanh: a*sigmoid(a) = 0.5a*tanh(0.5a) + 0.5a   (1 MUFU)
__device__ __forceinline__ float silu_fast(float a) {
    float h = 0.5f * a;
    return fmaf(h, tanh_fast(h), h);
}

// fatt = sigmoid(a) - 0.5, exp-based (accurate: 2 MUFU)
__device__ __forceinline__ float fatt_fast(float a) {
    float e = __expf(-a);
    return __fdividef(1.0f, 1.0f + e) - 0.5f;
}

__device__ __forceinline__ float outval(float x0, float x1, float x2) {
    float f1 = silu_fast(x1);
    float f2 = silu_fast(x2);
    return (f1 + x0) * fatt_fast(f2);
}

__global__ __launch_bounds__(256, 8)
void ablock_kernel(const float* __restrict__ x, float* __restrict__ out) {
    const int lane = threadIdx.x & 31;
    const int wrp  = threadIdx.x >> 5;
    const int g    = blockIdx.x * 8 + wrp;          // warp group id < 81920
    const int i0   = (g & 31) << 2;                 // first of 4 rows
    const int bc   = g >> 5;                        // plane index (b*320+c)
    const int s    = bc % 5;                        // (bc%320)%5 == bc%5 since 5|320
    const float* plane = x   + (long long)bc * PLANE;
    float*      oplane = out + (long long)bc * PLANE;
    const int j0 = lane << 2;

    #pragma unroll
    for (int t = 0; t < 4; t++) {
        const int i = i0 + t;
        const float* row = plane + i * WW;
        float4 a = *(const float4*)(row + j0);
        float4 r;

        if (s == 4) {
            r.x = outval(a.x, a.x, a.x);
            r.y = outval(a.y, a.y, a.y);
            r.z = outval(a.z, a.z, a.z);
            r.w = outval(a.w, a.w, a.w);
        } else if (s == 0) {
            float4 b = *(const float4*)(row + ((j0 + 4) & 127));
            r.x = outval(a.x, a.y, a.z);
            r.y = outval(a.y, a.z, a.w);
            r.z = outval(a.z, a.w, b.x);
            r.w = outval(a.w, b.x, b.y);
        } else if (s == 1) {
            float4 b = *(const float4*)(row + ((j0 + 124) & 127));
            r.x = outval(a.x, b.w, b.z);
            r.y = outval(a.y, a.x, b.w);
            r.z = outval(a.z, a.y, a.x);
            r.w = outval(a.w, a.z, a.y);
        } else if (s == 2) {
            const float* r1 = plane + (((i + 1) & 127) * WW);
            const float* r2 = plane + (((i + 2) & 127) * WW);
            float4 b = *(const float4*)(r1 + j0);
            float4 d = *(const float4*)(r2 + j0);
            r.x = outval(a.x, b.x, d.x);
            r.y = outval(a.y, b.y, d.y);
            r.z = outval(a.z, b.z, d.z);
            r.w = outval(a.w, b.w, d.w);
        } else {
            const float* r1 = plane + (((i + 127) & 127) * WW);
            const float* r2 = plane + (((i + 126) & 127) * WW);
            float4 b = *(const float4*)(r1 + j0);
            float4 d = *(const float4*)(r2 + j0);
            r.x = outval(a.x, b.x, d.x);
            r.y = outval(a.y, b.y, d.y);
            r.z = outval(a.z, b.z, d.z);
            r.w = outval(a.w, b.w, d.w);
        }

        *(float4*)(oplane + i * WW + j0) = r;
    }
}

extern "C" void kernel_launch(void* const* d_in, const int* in_sizes, int n_in,
                              void* d_out, int out_size) {
    const float* x = (const float*)d_in[0];
    float* out = (float*)d_out;
    dim3 grid(NGROUPS / 8);   // 10240 blocks
    dim3 block(256);
    ablock_kernel<<<grid, block>>>(x, out);
}

// round 3
// speedup vs baseline: 1.1013x; 1.0249x over previous
#include <cuda_runtime.h>
#include <cuda_bf16.h>

// x: (8, 320, 128, 128) fp32, out same.
// out(c,p) = (silu(x[S(p)]) + x[p]) * (sigmoid(silu(x[S2(p)])) - 0.5)
// S per channel: c%5==0: j+1 ; 1: j-1 ; 2: i+1 ; 3: i-1 ; 4: identity (circular)

#define HH 128
#define WW 128
#define PLANE (HH*WW)
#define NCH 320
#define NGROUPS (8*NCH*(HH/4))   // warp = 4 rows; 81920 groups

__device__ __forceinline__ float tanhapx(float a) {
    float r;
    asm("tanh.approx.f32 %0, %1;" : "=f"(r) : "f"(a));
    return r;
}
// silu(a) = 0.5a*tanh(0.5a) + 0.5a        (1 MUFU)
__device__ __forceinline__ float silu_f(float a) {
    float h = 0.5f * a;
    return fmaf(h, tanhapx(h), h);
}
// sigmoid(a) - 0.5 = 0.5*tanh(0.5a)       (1 MUFU)
__device__ __forceinline__ float fatt_f(float a) {
    return 0.5f * tanhapx(0.5f * a);
}
__device__ __forceinline__ float4 silu4(float4 v) {
    return make_float4(silu_f(v.x), silu_f(v.y), silu_f(v.z), silu_f(v.w));
}
// r = (f1 + x0) * fatt(f2), componentwise
__device__ __forceinline__ float4 comb4(float4 x0, float4 f1, float4 f2) {
    return make_float4((f1.x + x0.x) * fatt_f(f2.x),
                       (f1.y + x0.y) * fatt_f(f2.y),
                       (f1.z + x0.z) * fatt_f(f2.z),
                       (f1.w + x0.w) * fatt_f(f2.w));
}

__global__ __launch_bounds__(256)
void ablock_kernel(const float* __restrict__ x, float* __restrict__ out) {
    const int lane = threadIdx.x & 31;
    const int wrp  = threadIdx.x >> 5;
    const int g    = blockIdx.x * 8 + wrp;          // < 81920
    const int i0   = (g & 31) << 2;                 // first of 4 rows
    const int bc   = g >> 5;                        // plane index
    const int s    = bc % 5;                        // == c%5 since 5|320
    const float* plane = x   + (long long)bc * PLANE;
    float*      oplane = out + (long long)bc * PLANE;
    const int j0 = lane << 2;

    if (s == 0) {
        // S: j+1. chain v = [a.x a.y a.z a.w b.x b.y], f1_k=silu(v[k+1]), f2_k=silu(v[k+2])
        #pragma unroll
        for (int t = 0; t < 4; t++) {
            const float* row = plane + (i0 + t) * WW;
            float4 a = *(const float4*)(row + j0);
            float4 b = *(const float4*)(row + ((j0 + 4) & 127));
            float s1 = silu_f(a.y), s2 = silu_f(a.z), s3 = silu_f(a.w);
            float s4 = silu_f(b.x), s5 = silu_f(b.y);
            float4 r;
            r.x = (s1 + a.x) * fatt_f(s2);
            r.y = (s2 + a.y) * fatt_f(s3);
            r.z = (s3 + a.z) * fatt_f(s4);
            r.w = (s4 + a.w) * fatt_f(s5);
            *(float4*)(oplane + (i0 + t) * WW + j0) = r;
        }
    } else if (s == 1) {
        // S: j-1. silus of [b.z b.w a.x a.y a.z]
        #pragma unroll
        for (int t = 0; t < 4; t++) {
            const float* row = plane + (i0 + t) * WW;
            float4 a = *(const float4*)(row + j0);
            float4 b = *(const float4*)(row + ((j0 + 124) & 127));
            float s0 = silu_f(b.z), s1 = silu_f(b.w), s2 = silu_f(a.x);
            float s3 = silu_f(a.y), s4 = silu_f(a.z);
            float4 r;
            r.x = (s1 + a.x) * fatt_f(s0);
            r.y = (s2 + a.y) * fatt_f(s1);
            r.z = (s3 + a.z) * fatt_f(s2);
            r.w = (s4 + a.w) * fatt_f(s3);
            *(float4*)(oplane + (i0 + t) * WW + j0) = r;
        }
    } else if (s == 2) {
        // S: i+1. sliding window over rows i0 .. i0+5
        float4 cur = *(const float4*)(plane + i0 * WW + j0);
        float4 n1  = *(const float4*)(plane + ((i0 + 1) & 127) * WW + j0);
        float4 n2  = *(const float4*)(plane + ((i0 + 2) & 127) * WW + j0);
        float4 s1v = silu4(n1);
        float4 s2v = silu4(n2);
        #pragma unroll
        for (int t = 0; t < 4; t++) {
            *(float4*)(oplane + (i0 + t) * WW + j0) = comb4(cur, s1v, s2v);
            if (t < 3) {
                cur = n1; n1 = n2; s1v = s2v;
                n2 = *(const float4*)(plane + ((i0 + t + 3) & 127) * WW + j0);
                s2v = silu4(n2);
            }
        }
    } else if (s == 3) {
        // S: i-1. f1_t = silu(row i0+t-1), f2_t = silu(row i0+t-2)
        float4 sm2 = silu4(*(const float4*)(plane + ((i0 + 126) & 127) * WW + j0));
        float4 sm1 = silu4(*(const float4*)(plane + ((i0 + 127) & 127) * WW + j0));
        float4 cur = *(const float4*)(plane + i0 * WW + j0);
        #pragma unroll
        for (int t = 0; t < 4; t++) {
            *(float4*)(oplane + (i0 + t) * WW + j0) = comb4(cur, sm1, sm2);
            if (t < 3) {
                sm2 = sm1;
                sm1 = silu4(cur);
                cur = *(const float4*)(plane + (i0 + t + 1) * WW + j0);
            }
        }
    } else {
        // identity: f1 = f2 = silu(a)
        #pragma unroll
        for (int t = 0; t < 4; t++) {
            const float* row = plane + (i0 + t) * WW;
            float4 a = *(const float4*)(row + j0);
            float4 f = silu4(a);
            *(float4*)(oplane + (i0 + t) * WW + j0) = comb4(a, f, f);
        }
    }
}

extern "C" void kernel_launch(void* const* d_in, const int* in_sizes, int n_in,
                              void* d_out, int out_size) {
    const float* x = (const float*)d_in[0];
    float* out = (float*)d_out;
    dim3 grid(NGROUPS / 8);   // 10240 blocks
    dim3 block(256);
    ablock_kernel<<<grid, block>>>(x, out);
}